// round 14
// baseline (speedup 1.0000x reference)
#include <cuda_runtime.h>
#include <cuda_fp16.h>
#include <cstdint>

typedef unsigned int u32;

#define BB 8
#define SS 4096
#define DD 64
#define KT 32
#define NTILE (SS/KT)
#define QROWS 64
#define NT 64
#define LOG2E 1.4426950408889634f
#define LIMBSTR (BB*SS*DD/2)     // u32 elements per limb plane

// fp16 limb arrays, packed f16x2.
// g_lq: Q-role hi limb, pre-scaled by log2(e).  g_lk: KV-role, [hi | lo] planes.
__device__ u32 g_lq[2][LIMBSTR];        // 8 MB
__device__ u32 g_lk[2][2*LIMBSTR];      // 16 MB

__device__ __forceinline__ u32 s2u(const void* p){
    u32 a; asm("{ .reg .u64 t; cvta.to.shared.u64 t, %1; cvt.u32.u64 %0, t; }":"=r"(a):"l"(p));
    return a;
}
__device__ __forceinline__ u32 pkhf(float lo, float hi){
    __half2 h = __floats2half2_rn(lo, hi);
    return *reinterpret_cast<u32*>(&h);
}
__device__ __forceinline__ float ex2f(float a){
    float d; asm("ex2.approx.f32 %0, %1;" : "=f"(d) : "f"(a)); return d;
}
__device__ __forceinline__ void ldsm4(u32 a, u32* r){
    asm volatile("ldmatrix.sync.aligned.m8n8.x4.shared.b16 {%0,%1,%2,%3},[%4];"
        : "=r"(r[0]),"=r"(r[1]),"=r"(r[2]),"=r"(r[3]) : "r"(a));
}
__device__ __forceinline__ void ldsm4t(u32 a, u32* r){
    asm volatile("ldmatrix.sync.aligned.m8n8.x4.trans.shared.b16 {%0,%1,%2,%3},[%4];"
        : "=r"(r[0]),"=r"(r[1]),"=r"(r[2]),"=r"(r[3]) : "r"(a));
}
__device__ __forceinline__ void mma_hf(float* d, const u32* a, const u32* b){
    asm volatile("mma.sync.aligned.m16n8k16.row.col.f32.f16.f16.f32 "
        "{%0,%1,%2,%3},{%4,%5,%6,%7},{%8,%9},{%0,%1,%2,%3};"
        : "+f"(d[0]),"+f"(d[1]),"+f"(d[2]),"+f"(d[3])
        : "r"(a[0]),"r"(a[1]),"r"(a[2]),"r"(a[3]),"r"(b[0]),"r"(b[1]));
}
__device__ __forceinline__ u32 swa(u32 row, u32 chunk){
    return row*128u + ((chunk ^ (row & 7u)) << 4);
}
#define CP16(saddr, gptr) \
    asm volatile("cp.async.cg.shared.global [%0], [%1], 16;" :: "r"(saddr), "l"(gptr))

// ---------------- pre-pass: fp32 -> fp16 limbs (KV hi/lo raw, Q hi log2e-scaled) ----------------
__global__ __launch_bounds__(256)
void cvt_kernel(const float* __restrict__ x, const float* __restrict__ y)
{
    int i = blockIdx.x * 256 + threadIdx.x;          // handles 8 floats
    const float4* s4 = (const float4*)(blockIdx.y ? y : x);
    float4 a = s4[2*i], b = s4[2*i+1];
    float f[8] = {a.x,a.y,a.z,a.w,b.x,b.y,b.z,b.w};
    uint4 khi, klo, qhi;
    u32 *pkh = &khi.x, *pkl = &klo.x, *pqh = &qhi.x;
#pragma unroll
    for (int k = 0; k < 4; k++){
        float f0 = f[2*k], f1 = f[2*k+1];
        __half2 h = __floats2half2_rn(f0, f1);
        pkh[k] = *reinterpret_cast<u32*>(&h);
        pkl[k] = pkhf(f0 - __low2float(h), f1 - __high2float(h));
        pqh[k] = pkhf(f0 * LOG2E, f1 * LOG2E);
    }
    ((uint4*)g_lk[blockIdx.y])[i] = khi;
    ((uint4*)g_lk[blockIdx.y])[LIMBSTR/4 + i] = klo;
    ((uint4*)g_lq[blockIdx.y])[i] = qhi;
}

// ---------------- main flash-attention kernel: 2 warps x 32 q-rows ----------------
__global__ __launch_bounds__(NT, 4)
void bimodal_mma_kernel(const float* __restrict__ x, const float* __restrict__ y,
                        float* __restrict__ out)
{
    __shared__ __align__(1024) char smem[16384];  // [buf][limb][4KB]; Q stage reuses buf area
    const int tid = threadIdx.x;
    const int lane = tid & 31, warp = tid >> 5;
    const int dir = blockIdx.y, b = blockIdx.z;
    const int qi = dir, ki = 1 - dir;
    const float* Qf = (dir == 0) ? x : y;  // fp32 q for epilogue multiply
    const int rowBase = blockIdx.x * QROWS;
    const u32 sb = s2u(smem);

    const int g = lane >> 2, tg = lane & 3;
    const u32 sub = (u32)(lane >> 3), lr = (u32)(lane & 7);

    // ---- hoisted addresses ----
    // kv cp.async: 8 chunks/thread; one base pointer + u32 offsets
    const u32* kbase = g_lk[ki] + (size_t)b * SS * 32;
    u32 soff[8], goff[8];
#pragma unroll
    for (int k = 0; k < 8; k++){
        u32 j = (u32)tid + 64u*k;                // 0..511
        u32 limb = j >> 8, r = (j >> 3) & 31u, c = j & 7u;
        soff[k] = limb*4096u + swa(r, c);
        goff[k] = limb*(u32)LIMBSTR + r*32u + c*4u;
    }
    u32 qko[4][2];
    {
        u32 r0 = (sub >> 1)*8u + lr;
#pragma unroll
        for (int kt = 0; kt < 4; kt++){
            u32 c = (u32)(kt*2) + (sub & 1u);
            qko[kt][0] = swa(r0, c);
            qko[kt][1] = swa(r0 + 16u, c);
        }
    }
    u32 pvo[2][4];
#pragma unroll
    for (int kt2 = 0; kt2 < 2; kt2++){
        u32 r = (u32)(kt2*16) + (sub & 1u)*8u + lr;
#pragma unroll
        for (int nt = 0; nt < 4; nt++)
            pvo[kt2][nt] = swa(r, (u32)(nt*2) + (sub >> 1));
    }

    // ---- stage Q hi limb (64 rows = 8KB), ldmatrix fragments (2 m-tiles) ----
    u32 qh[2][4][4];
    {
        const u32* qbase = g_lq[qi] + (size_t)(b*SS + rowBase) * 32;
#pragma unroll
        for (int k = 0; k < 8; k++){
            u32 j = (u32)tid + 64u*k;            // 0..511
            u32 r = (j >> 3) & 63u, c = j & 7u;
            CP16(sb + swa(r, c), qbase + r*32u + c*4u);
        }
        asm volatile("cp.async.commit_group;");
        asm volatile("cp.async.wait_group 0;");
        __syncthreads();
#pragma unroll
        for (int m = 0; m < 2; m++){
            u32 r = (u32)(warp*32 + m*16) + (sub & 1u)*8u + lr;
#pragma unroll
            for (int kt = 0; kt < 4; kt++)
                ldsm4(sb + swa(r, (u32)(kt*2) + (sub >> 1)), qh[m][kt]);
        }
        __syncthreads();
    }

    // ---- KV pipeline prologue: tile 0 -> buf 0 ----
#pragma unroll
    for (int k = 0; k < 8; k++)
        CP16(sb + soff[k], kbase + goff[k]);
    kbase += 1024;
    asm volatile("cp.async.commit_group;");

    float accO[2][8][4];
#pragma unroll
    for (int m = 0; m < 2; m++)
#pragma unroll
        for (int n = 0; n < 8; n++)
#pragma unroll
            for (int i = 0; i < 4; i++) accO[m][n][i] = 0.0f;
    float lsum[2][2] = {{0.f,0.f},{0.f,0.f}};
    float mx[2][2] = {{0.f,0.f},{0.f,0.f}};     // quantized running max (exp2 domain)

#pragma unroll 1
    for (int t = 0; t < NTILE; t++){
        asm volatile("cp.async.wait_group 0;");
        __syncthreads();
        if (t < NTILE-1){
            u32 boff = (u32)((t+1) & 1) * 8192u;
#pragma unroll
            for (int k = 0; k < 8; k++)
                CP16(sb + boff + soff[k], kbase + goff[k]);
            asm volatile("cp.async.commit_group;");
        }
        kbase += 1024;                            // unconditional advance

        const u32 kb = sb + (u32)(t & 1) * 8192u;   // hi limb; lo at +4096

        // ---- QK (exp2 domain): S = Qh*Kh + Qh*Kl, 2 m-tiles ----
        float S[2][4][4];
#pragma unroll
        for (int m = 0; m < 2; m++)
#pragma unroll
            for (int n = 0; n < 4; n++)
#pragma unroll
                for (int i = 0; i < 4; i++) S[m][n][i] = 0.0f;

#pragma unroll
        for (int kt = 0; kt < 4; kt++){
            u32 Bh[8], Bl[8];
            ldsm4(kb +         qko[kt][0], Bh);
            ldsm4(kb +         qko[kt][1], Bh+4);
            ldsm4(kb + 4096u + qko[kt][0], Bl);
            ldsm4(kb + 4096u + qko[kt][1], Bl+4);
#pragma unroll
            for (int m = 0; m < 2; m++)
#pragma unroll
                for (int n = 0; n < 4; n++){
                    mma_hf(S[m][n], qh[m][kt], &Bh[n*2]);
                    mma_hf(S[m][n], qh[m][kt], &Bl[n*2]);
                }
        }

        // ---- lazy quantized max + p = 2^(s-m), per m-tile ----
        u32 pf[2][2][4];
#pragma unroll
        for (int m = 0; m < 2; m++){
            float rm0 = fmaxf(fmaxf(S[m][0][0], S[m][0][1]), fmaxf(S[m][1][0], S[m][1][1]));
            float rm1 = fmaxf(fmaxf(S[m][0][2], S[m][0][3]), fmaxf(S[m][1][2], S[m][1][3]));
            rm0 = fmaxf(rm0, fmaxf(fmaxf(S[m][2][0], S[m][2][1]), fmaxf(S[m][3][0], S[m][3][1])));
            rm1 = fmaxf(rm1, fmaxf(fmaxf(S[m][2][2], S[m][2][3]), fmaxf(S[m][3][2], S[m][3][3])));
            rm0 = fmaxf(rm0, __shfl_xor_sync(0xffffffffu, rm0, 1));
            rm1 = fmaxf(rm1, __shfl_xor_sync(0xffffffffu, rm1, 1));
            rm0 = fmaxf(rm0, __shfl_xor_sync(0xffffffffu, rm0, 2));
            rm1 = fmaxf(rm1, __shfl_xor_sync(0xffffffffu, rm1, 2));
            if (rm0 > mx[m][0]){
                float mn = ceilf(rm0 * 0.125f) * 8.0f;
                float c = ex2f(mx[m][0] - mn);     // exact power of 2
                mx[m][0] = mn; lsum[m][0] *= c;
#pragma unroll
                for (int n = 0; n < 8; n++){ accO[m][n][0] *= c; accO[m][n][1] *= c; }
            }
            if (rm1 > mx[m][1]){
                float mn = ceilf(rm1 * 0.125f) * 8.0f;
                float c = ex2f(mx[m][1] - mn);
                mx[m][1] = mn; lsum[m][1] *= c;
#pragma unroll
                for (int n = 0; n < 8; n++){ accO[m][n][2] *= c; accO[m][n][3] *= c; }
            }
#pragma unroll
            for (int j = 0; j < 4; j++){
                float e0 = ex2f(S[m][j][0] - mx[m][0]), e1 = ex2f(S[m][j][1] - mx[m][0]);
                float e2 = ex2f(S[m][j][2] - mx[m][1]), e3 = ex2f(S[m][j][3] - mx[m][1]);
                lsum[m][0] += e0 + e1;
                lsum[m][1] += e2 + e3;
                pf[m][j>>1][(j&1)*2+0] = pkhf(e0, e1);
                pf[m][j>>1][(j&1)*2+1] = pkhf(e2, e3);
            }
        }

        // ---- PV: O += P * Vh (single-limb V), V fragments shared across m ----
#pragma unroll
        for (int kt2 = 0; kt2 < 2; kt2++){
#pragma unroll
            for (int nt = 0; nt < 4; nt++){
                u32 Vh[4];
                ldsm4t(kb + pvo[kt2][nt], Vh);
#pragma unroll
                for (int m = 0; m < 2; m++){
                    mma_hf(accO[m][nt*2+0], pf[m][kt2], &Vh[0]);
                    mma_hf(accO[m][nt*2+1], pf[m][kt2], &Vh[2]);
                }
            }
        }
    }

    // ---------------- epilogue ----------------
#pragma unroll
    for (int m = 0; m < 2; m++)
#pragma unroll
        for (int hh = 0; hh < 2; hh++){
            float v = lsum[m][hh];
            v += __shfl_xor_sync(0xffffffffu, v, 1);
            v += __shfl_xor_sync(0xffffffffu, v, 2);
            lsum[m][hh] = v;
        }

#pragma unroll
    for (int m = 0; m < 2; m++)
#pragma unroll
        for (int hh = 0; hh < 2; hh++){
            int row = rowBase + warp*32 + m*16 + g + hh*8;
            float inv = 1.0f / lsum[m][hh];
            const float2* qp = (const float2*)(Qf + ((size_t)b*SS + row)*DD);
            float* op = out + ((size_t)b*SS + row)*128 + dir*64;
#pragma unroll
            for (int n = 0; n < 8; n++){
                int col = n*8 + tg*2;
                float2 qv = qp[col >> 1];
                float2 w;
                w.x = accO[m][n][hh*2+0] * inv * qv.x;
                w.y = accO[m][n][hh*2+1] * inv * qv.y;
                *(float2*)(op + col) = w;
            }
        }
}

extern "C" void kernel_launch(void* const* d_in, const int* in_sizes, int n_in,
                              void* d_out, int out_size)
{
    const float* x = (const float*)d_in[0];
    const float* y = (const float*)d_in[1];
    float* out = (float*)d_out;

    dim3 cgrid(BB*SS*DD/8/256, 2);               // limb split pre-pass
    cvt_kernel<<<cgrid, 256>>>(x, y);

    dim3 grid(SS / QROWS, 2, BB);                // 64 x 2 x 8 = 1024 blocks, 64 threads
    bimodal_mma_kernel<<<grid, NT>>>(x, y, out);
}

// round 15
// speedup vs baseline: 1.1145x; 1.1145x over previous
#include <cuda_runtime.h>
#include <cuda_fp16.h>
#include <cstdint>

typedef unsigned int u32;

#define BB 8
#define SS 4096
#define DD 64
#define KT 32
#define NTILE (SS/KT)
#define QROWS 64
#define LOG2E 1.4426950408889634f
#define LIMBSTR (BB*SS*DD/2)     // u32 elements per limb plane

// fp16 limb arrays, packed f16x2.
// g_lq: Q-role, log2e-scaled, [hi | lo] planes.  g_lk: KV-role hi limb only, raw.
__device__ u32 g_lq[2][2*LIMBSTR];      // 16 MB
__device__ u32 g_lk[2][LIMBSTR];        // 8 MB

__device__ __forceinline__ u32 s2u(const void* p){
    u32 a; asm("{ .reg .u64 t; cvta.to.shared.u64 t, %1; cvt.u32.u64 %0, t; }":"=r"(a):"l"(p));
    return a;
}
__device__ __forceinline__ u32 pkhf(float lo, float hi){
    __half2 h = __floats2half2_rn(lo, hi);
    return *reinterpret_cast<u32*>(&h);
}
__device__ __forceinline__ float ex2f(float a){
    float d; asm("ex2.approx.f32 %0, %1;" : "=f"(d) : "f"(a)); return d;
}
__device__ __forceinline__ void ldsm4(u32 a, u32* r){
    asm volatile("ldmatrix.sync.aligned.m8n8.x4.shared.b16 {%0,%1,%2,%3},[%4];"
        : "=r"(r[0]),"=r"(r[1]),"=r"(r[2]),"=r"(r[3]) : "r"(a));
}
__device__ __forceinline__ void ldsm4t(u32 a, u32* r){
    asm volatile("ldmatrix.sync.aligned.m8n8.x4.trans.shared.b16 {%0,%1,%2,%3},[%4];"
        : "=r"(r[0]),"=r"(r[1]),"=r"(r[2]),"=r"(r[3]) : "r"(a));
}
__device__ __forceinline__ void mma_hf(float* d, const u32* a, const u32* b){
    asm volatile("mma.sync.aligned.m16n8k16.row.col.f32.f16.f16.f32 "
        "{%0,%1,%2,%3},{%4,%5,%6,%7},{%8,%9},{%0,%1,%2,%3};"
        : "+f"(d[0]),"+f"(d[1]),"+f"(d[2]),"+f"(d[3])
        : "r"(a[0]),"r"(a[1]),"r"(a[2]),"r"(a[3]),"r"(b[0]),"r"(b[1]));
}
__device__ __forceinline__ u32 swa(u32 row, u32 chunk){
    return row*128u + ((chunk ^ (row & 7u)) << 4);
}
#define CP16(saddr, gptr) \
    asm volatile("cp.async.cg.shared.global [%0], [%1], 16;" :: "r"(saddr), "l"(gptr))

// ---------------- pre-pass: Q -> scaled fp16 hi/lo limbs, KV -> fp16 hi limb ----------------
__global__ __launch_bounds__(256)
void cvt_kernel(const float* __restrict__ x, const float* __restrict__ y)
{
    int i = blockIdx.x * 256 + threadIdx.x;          // handles 8 floats
    const float4* s4 = (const float4*)(blockIdx.y ? y : x);
    float4 a = s4[2*i], b = s4[2*i+1];
    float f[8] = {a.x,a.y,a.z,a.w,b.x,b.y,b.z,b.w};
    uint4 khi, qhi, qlo;
    u32 *pkh = &khi.x, *pqh = &qhi.x, *pql = &qlo.x;
#pragma unroll
    for (int k = 0; k < 4; k++){
        float f0 = f[2*k], f1 = f[2*k+1];
        __half2 h = __floats2half2_rn(f0, f1);
        pkh[k] = *reinterpret_cast<u32*>(&h);
        float g0 = f0 * LOG2E, g1 = f1 * LOG2E;
        __half2 g = __floats2half2_rn(g0, g1);
        pqh[k] = *reinterpret_cast<u32*>(&g);
        pql[k] = pkhf(g0 - __low2float(g), g1 - __high2float(g));
    }
    ((uint4*)g_lk[blockIdx.y])[i] = khi;
    ((uint4*)g_lq[blockIdx.y])[i] = qhi;
    ((uint4*)g_lq[blockIdx.y])[LIMBSTR/4 + i] = qlo;
}

// ---------------- main flash-attention kernel ----------------
__global__ __launch_bounds__(128, 3)
void bimodal_mma_kernel(const float* __restrict__ x, const float* __restrict__ y,
                        float* __restrict__ out)
{
    __shared__ __align__(1024) char smem[16384];  // kv: 2 x 4KB double buffer; Q staging reuses 8KB
    const int tid = threadIdx.x;
    const int lane = tid & 31, warp = tid >> 5;
    const int dir = blockIdx.y, b = blockIdx.z;
    const int qi = dir, ki = 1 - dir;
    const float* Qf = (dir == 0) ? x : y;  // fp32 q for epilogue multiply
    const int rowBase = blockIdx.x * QROWS;
    const u32 sb = s2u(smem);

    const int g = lane >> 2, tg = lane & 3;
    const u32 sub = (u32)(lane >> 3), lr = (u32)(lane & 7);

    // ---- hoisted addresses ----
    // kv cp.async: 4KB/tile = 2 chunks/thread
    const u32* kbase = g_lk[ki] + (size_t)b * SS * 32;
    u32 soff[2], goff[2];
#pragma unroll
    for (int k = 0; k < 2; k++){
        u32 j = (u32)tid + 128u*k;               // 0..255
        u32 r = (j >> 3) & 31u, c = j & 7u;
        soff[k] = swa(r, c);
        goff[k] = r*32u + c*4u;
    }
    u32 qko[4][2];
    {
        u32 r0 = (sub >> 1)*8u + lr;
#pragma unroll
        for (int kt = 0; kt < 4; kt++){
            u32 c = (u32)(kt*2) + (sub & 1u);
            qko[kt][0] = swa(r0, c);
            qko[kt][1] = swa(r0 + 16u, c);
        }
    }
    u32 pvo[2][4];
#pragma unroll
    for (int kt2 = 0; kt2 < 2; kt2++){
        u32 r = (u32)(kt2*16) + (sub & 1u)*8u + lr;
#pragma unroll
        for (int nt = 0; nt < 4; nt++)
            pvo[kt2][nt] = swa(r, (u32)(nt*2) + (sub >> 1));
    }

    // ---- stage Q hi then lo limb (8KB each, reusing same smem), ldmatrix fragments ----
    u32 qh[4][4], ql[4][4];
    {
        const u32* qbase = g_lq[qi] + (size_t)(b*SS + rowBase) * 32;
        u32 qr = (u32)(warp*16) + (sub & 1u)*8u + lr;
#pragma unroll
        for (int limb = 0; limb < 2; limb++){
#pragma unroll
            for (int k = 0; k < 4; k++){
                u32 j = (u32)tid + 128u*k;       // 0..511
                u32 r = (j >> 3) & 63u, c = j & 7u;
                CP16(sb + swa(r, c), qbase + (size_t)limb*LIMBSTR + r*32u + c*4u);
            }
            asm volatile("cp.async.commit_group;");
            asm volatile("cp.async.wait_group 0;");
            __syncthreads();
            u32 (*dst)[4] = limb ? ql : qh;
#pragma unroll
            for (int kt = 0; kt < 4; kt++)
                ldsm4(sb + swa(qr, (u32)(kt*2) + (sub >> 1)), dst[kt]);
            asm volatile("" ::: "memory");
            __syncthreads();
        }
    }

    // ---- KV pipeline prologue: tile 0 -> buf 0 ----
#pragma unroll
    for (int k = 0; k < 2; k++)
        CP16(sb + soff[k], kbase + goff[k]);
    kbase += 1024;
    asm volatile("cp.async.commit_group;");

    float accO[8][4];
#pragma unroll
    for (int n = 0; n < 8; n++)
#pragma unroll
        for (int i = 0; i < 4; i++) accO[n][i] = 0.0f;
    float lsum[2] = {0.f, 0.f};
    float m0 = 0.0f, m1 = 0.0f;          // quantized running max (exp2 domain)

#pragma unroll 1
    for (int t = 0; t < NTILE; t++){
        asm volatile("cp.async.wait_group 0;");
        __syncthreads();
        if (t < NTILE-1){
            u32 boff = (u32)((t+1) & 1) * 4096u;
#pragma unroll
            for (int k = 0; k < 2; k++)
                CP16(sb + boff + soff[k], kbase + goff[k]);
            asm volatile("cp.async.commit_group;");
        }
        kbase += 1024;                            // unconditional advance

        const u32 kb = sb + (u32)(t & 1) * 4096u;   // single (hi) limb tile

        // ---- QK (exp2 domain): S = Qh*Kh + Ql*Kh ----
        float S[4][4];
#pragma unroll
        for (int n = 0; n < 4; n++)
#pragma unroll
            for (int i = 0; i < 4; i++) S[n][i] = 0.0f;

#pragma unroll
        for (int kt = 0; kt < 4; kt++){
            u32 Bh[8];
            ldsm4(kb + qko[kt][0], Bh);
            ldsm4(kb + qko[kt][1], Bh+4);
#pragma unroll
            for (int n = 0; n < 4; n++){
                mma_hf(S[n], qh[kt], &Bh[n*2]);
                mma_hf(S[n], ql[kt], &Bh[n*2]);
            }
        }

        // ---- lazy quantized max (rare rescale) ----
        float a0 = fmaxf(S[0][0], S[0][1]), b0 = fmaxf(S[1][0], S[1][1]);
        float c0f = fmaxf(S[2][0], S[2][1]), d0 = fmaxf(S[3][0], S[3][1]);
        float a1 = fmaxf(S[0][2], S[0][3]), b1 = fmaxf(S[1][2], S[1][3]);
        float c1f = fmaxf(S[2][2], S[2][3]), d1 = fmaxf(S[3][2], S[3][3]);
        float rm0 = fmaxf(fmaxf(a0, b0), fmaxf(c0f, d0));
        float rm1 = fmaxf(fmaxf(a1, b1), fmaxf(c1f, d1));
        rm0 = fmaxf(rm0, __shfl_xor_sync(0xffffffffu, rm0, 1));
        rm1 = fmaxf(rm1, __shfl_xor_sync(0xffffffffu, rm1, 1));
        rm0 = fmaxf(rm0, __shfl_xor_sync(0xffffffffu, rm0, 2));
        rm1 = fmaxf(rm1, __shfl_xor_sync(0xffffffffu, rm1, 2));
        if (rm0 > m0){
            float mn = ceilf(rm0 * 0.125f) * 8.0f;
            float c = ex2f(m0 - mn);           // exact power of 2
            m0 = mn; lsum[0] *= c;
#pragma unroll
            for (int n = 0; n < 8; n++){ accO[n][0] *= c; accO[n][1] *= c; }
        }
        if (rm1 > m1){
            float mn = ceilf(rm1 * 0.125f) * 8.0f;
            float c = ex2f(m1 - mn);
            m1 = mn; lsum[1] *= c;
#pragma unroll
            for (int n = 0; n < 8; n++){ accO[n][2] *= c; accO[n][3] *= c; }
        }

        // ---- p = 2^(s - m), single fp16 limb ----
        u32 pf[2][4];
#pragma unroll
        for (int j = 0; j < 4; j++){
            float e0 = ex2f(S[j][0] - m0), e1 = ex2f(S[j][1] - m0);
            float e2 = ex2f(S[j][2] - m1), e3 = ex2f(S[j][3] - m1);
            lsum[0] += e0 + e1;
            lsum[1] += e2 + e3;
            pf[j>>1][(j&1)*2+0] = pkhf(e0, e1);
            pf[j>>1][(j&1)*2+1] = pkhf(e2, e3);
        }

        // ---- PV: O += P * Vh (single-limb V, same buffer) ----
#pragma unroll
        for (int kt2 = 0; kt2 < 2; kt2++){
#pragma unroll
            for (int nt = 0; nt < 4; nt++){
                u32 Vh[4];
                ldsm4t(kb + pvo[kt2][nt], Vh);
                mma_hf(accO[nt*2+0], pf[kt2], &Vh[0]);
                mma_hf(accO[nt*2+1], pf[kt2], &Vh[2]);
            }
        }
    }

    // ---------------- epilogue ----------------
    {
        float v0 = lsum[0], v1 = lsum[1];
        v0 += __shfl_xor_sync(0xffffffffu, v0, 1);
        v0 += __shfl_xor_sync(0xffffffffu, v0, 2);
        v1 += __shfl_xor_sync(0xffffffffu, v1, 1);
        v1 += __shfl_xor_sync(0xffffffffu, v1, 2);
        lsum[0] = v0; lsum[1] = v1;
    }

#pragma unroll
    for (int hh = 0; hh < 2; hh++){
        int row = rowBase + warp*16 + g + hh*8;
        float inv = 1.0f / lsum[hh];
        const float2* qp = (const float2*)(Qf + ((size_t)b*SS + row)*DD);
        float* op = out + ((size_t)b*SS + row)*128 + dir*64;
#pragma unroll
        for (int n = 0; n < 8; n++){
            int col = n*8 + tg*2;
            float2 qv = qp[col >> 1];
            float2 w;
            w.x = accO[n][hh*2+0] * inv * qv.x;
            w.y = accO[n][hh*2+1] * inv * qv.y;
            *(float2*)(op + col) = w;
        }
    }
}

extern "C" void kernel_launch(void* const* d_in, const int* in_sizes, int n_in,
                              void* d_out, int out_size)
{
    const float* x = (const float*)d_in[0];
    const float* y = (const float*)d_in[1];
    float* out = (float*)d_out;

    dim3 cgrid(BB*SS*DD/8/256, 2);               // limb split pre-pass
    cvt_kernel<<<cgrid, 256>>>(x, y);

    dim3 grid(SS / QROWS, 2, BB);                // 64 x 2 x 8 = 1024 blocks
    bimodal_mma_kernel<<<grid, 128>>>(x, y, out);
}